// round 4
// baseline (speedup 1.0000x reference)
#include <cuda_runtime.h>

// PlaneValidator: symmetric-chamfer between 1024 points and their per-plane
// reflections, then per-batch conf ranking + angular NMS.  Single fused kernel:
// last-arriving block performs the (warp-parallel) finalization.
//
//  - D[n,m] = |p_n - r_m|^2 is SYMMETRIC (reflection = involutive isometry),
//    so sde = 2 * mean_n min_m D.
//  - min_m (P2[n] + R2[m] - 2 p_n.r_m) = P2[n] + min_m (R2[m] - 2 p_n.r_m).
//  - Inner loop uses Blackwell packed f32x2 FMA: both rows of a thread advance
//    in one FFMA2 chain against a pre-duplicated shared tile:
//    2 LDS.128 + 3 FFMA2 + 2 FMNMX per 2 pairs.

#define NB 4
#define NPTS 1024
#define NH 16
#define THREADS 256
#define ROW_CHUNK 512           // 2 chunks per (b,h); 2 rows per thread
#define NBLOCKS (NB * NH * 2)   // 128

#define COS_THR 0.8660254037844387f
#define FULL 0xFFFFFFFFu

__device__ float g_part[NBLOCKS];   // per-block partial sums (rewritten every launch)
__device__ int   g_count = 0;       // arrival counter (self-resetting)

__device__ __forceinline__ unsigned long long fma2(
        unsigned long long a, unsigned long long b, unsigned long long c) {
    unsigned long long d;
    asm("fma.rn.f32x2 %0, %1, %2, %3;" : "=l"(d) : "l"(a), "l"(b), "l"(c));
    return d;
}
__device__ __forceinline__ unsigned long long pack2(float lo, float hi) {
    unsigned long long d;
    asm("mov.b64 %0, {%1, %2};" : "=l"(d) : "f"(lo), "f"(hi));
    return d;
}
__device__ __forceinline__ void unpack2(unsigned long long v, float& lo, float& hi) {
    asm("mov.b64 {%0, %1}, %2;" : "=f"(lo), "=f"(hi) : "l"(v));
}

__global__ __launch_bounds__(THREADS, 1) void plane_validator_kernel(
        const float* __restrict__ pts, const float* __restrict__ ypred,
        const int* __restrict__ thr_ptr, float* __restrict__ out) {
    const int bid = blockIdx.x;
    const int bh  = bid >> 1;          // (b,h) pair
    const int rc  = bid & 1;           // row chunk
    const int t   = threadIdx.x;

    // ---------------- chamfer phase ----------------
    const float* yp = ypred + bh * 4;
    const float nx = yp[0], ny = yp[1], nz = yp[2], dpl = yp[3];
    const float inv = 1.0f / sqrtf(nx * nx + ny * ny + nz * nz);
    const float nhx = nx * inv, nhy = ny * inv, nhz = nz * inv;
    const float dh  = dpl * inv;

    const float* pb = pts + (bh >> 4) * (NPTS * 3);

    // Duplicated column tile: per point m, two 16B records
    //   sB[2m]   = {-2rx,-2rx,-2ry,-2ry}   (as ulonglong2: .x = xx-pair, .y = yy-pair)
    //   sB[2m+1] = {-2rz,-2rz, r2 , r2 }   (.x = zz-pair, .y = r2-pair)
    __shared__ ulonglong2 sB[2 * NPTS];      // 32 KB
    for (int i = t; i < NPTS; i += THREADS) {
        float px = pb[i * 3 + 0], py = pb[i * 3 + 1], pz = pb[i * 3 + 2];
        float proj = fmaf(px, nhx, fmaf(py, nhy, fmaf(pz, nhz, dh)));
        float s = -2.0f * proj;
        float rx = fmaf(s, nhx, px);
        float ry = fmaf(s, nhy, py);
        float rz = fmaf(s, nhz, pz);
        float r2 = fmaf(rx, rx, fmaf(ry, ry, rz * rz));
        float mx = -2.0f * rx, my = -2.0f * ry, mz = -2.0f * rz;
        sB[2 * i]     = make_ulonglong2(pack2(mx, mx), pack2(my, my));
        sB[2 * i + 1] = make_ulonglong2(pack2(mz, mz), pack2(r2, r2));
    }

    // This thread's 2 rows (plain points), packed lane-pairwise
    float rxx[2], ryy[2], rzz[2], p2[2];
#pragma unroll
    for (int k = 0; k < 2; k++) {
        int r = rc * ROW_CHUNK + k * THREADS + t;
        float px = pb[r * 3 + 0], py = pb[r * 3 + 1], pz = pb[r * 3 + 2];
        rxx[k] = px; ryy[k] = py; rzz[k] = pz;
        p2[k] = fmaf(px, px, fmaf(py, py, pz * pz));
    }
    const unsigned long long ax01 = pack2(rxx[0], rxx[1]);
    const unsigned long long ay01 = pack2(ryy[0], ryy[1]);
    const unsigned long long az01 = pack2(rzz[0], rzz[1]);
    __syncthreads();

    // e_m = R2[m] - 2 p.r_m for both rows at once; row-min of D = p2 + min e
    float best0 = 3.4e38f, best1 = 3.4e38f;
#pragma unroll 8
    for (int m = 0; m < NPTS; m++) {
        ulonglong2 u0 = sB[2 * m];
        ulonglong2 u1 = sB[2 * m + 1];
        unsigned long long e = fma2(az01, u1.x, u1.y);
        e = fma2(ay01, u0.y, e);
        e = fma2(ax01, u0.x, e);
        float e0, e1;
        unpack2(e, e0, e1);
        best0 = fminf(best0, e0);
        best1 = fminf(best1, e1);
    }
    float acc = (best0 + p2[0]) + (best1 + p2[1]);

#pragma unroll
    for (int o = 16; o > 0; o >>= 1)
        acc += __shfl_down_sync(FULL, acc, o);

    __shared__ float wsum[THREADS / 32];
    __shared__ int s_last;
    if ((t & 31) == 0) wsum[t >> 5] = acc;
    __syncthreads();
    if (t == 0) {
        float s = 0.0f;
#pragma unroll
        for (int i = 0; i < THREADS / 32; i++) s += wsum[i];
        g_part[bid] = s;                         // raw sum of 512 row-mins
        __threadfence();                         // publish before arrival
        int old = atomicAdd(&g_count, 1);
        s_last = (old == NBLOCKS - 1);
        if (old == NBLOCKS - 1) g_count = 0;     // reset for next graph replay
    }
    __syncthreads();
    if (!s_last) return;

    // ---------------- finalize phase (last block only; lanes 0..63) ----------------
    __shared__ float s_ex[8][64];   // exchange: nx,ny,nz,px,py,pz,cf,sd by sorted pos

    const int l = t;
    float v_nx = 0, v_ny = 0, v_nz = 0, v_px = 0, v_py = 0, v_pz = 0, v_cf = 0, v_sd = 0;
    int pos = l & 15, b = l >> 4;

    if (l < 64) {
        // threshold: decode int32 vs float32 bit pattern defensively
        int tv = thr_ptr[0];
        float tf = __int_as_float(tv);
        float thr = (tf >= 1e-6f && tf <= 1e9f) ? tf : (float)tv;

        const float* yq = ypred + l * 4;
        float qx = yq[0], qy = yq[1], qz = yq[2], qd = yq[3];
        float qi = 1.0f / sqrtf(qx * qx + qy * qy + qz * qz);
        v_nx = qx * qi; v_ny = qy * qi; v_nz = qz * qi;
        float qdh = qd * qi;
        v_px = -qdh * v_nx; v_py = -qdh * v_ny; v_pz = -qdh * v_nz;

        // sde = 2 * mean(row mins): combine the two chunk partials
        volatile float* gp = g_part;
        v_sd = (gp[2 * l] + gp[2 * l + 1]) * (2.0f / (float)NPTS);

        // group min/max over 16 lanes
        float mn = v_sd, mx = v_sd;
#pragma unroll
        for (int o = 8; o > 0; o >>= 1) {
            mn = fminf(mn, __shfl_xor_sync(FULL, mn, o, 16));
            mx = fmaxf(mx, __shfl_xor_sync(FULL, mx, o, 16));
        }
        v_cf = 1.0f - (v_sd - mn) / (mx - mn);

        // stable descending rank (== stable argsort(-cf))
        int rank = 0;
#pragma unroll
        for (int j = 0; j < NH; j++) {
            float cfj = __shfl_sync(FULL, v_cf, j, 16);
            rank += (cfj > v_cf) || (cfj == v_cf && j < pos);
        }
        int slot = b * NH + rank;
        s_ex[0][slot] = v_nx; s_ex[1][slot] = v_ny; s_ex[2][slot] = v_nz;
        s_ex[3][slot] = v_px; s_ex[4][slot] = v_py; s_ex[5][slot] = v_pz;
        s_ex[6][slot] = v_cf; s_ex[7][slot] = v_sd;
        v_cf = thr;  // carry thr across the barrier
    }
    __syncthreads();
    if (l >= 64) return;

    float thr = v_cf;
    v_nx = s_ex[0][l]; v_ny = s_ex[1][l]; v_nz = s_ex[2][l];
    v_px = s_ex[3][l]; v_py = s_ex[4][l]; v_pz = s_ex[5][l];
    v_cf = s_ex[6][l]; v_sd = s_ex[7][l];

    // sequential NMS over sorted positions, live keep bits
    int keep = (v_sd <= thr);
#pragma unroll
    for (int i = 0; i < NH; i++) {
        int   ki  = __shfl_sync(FULL, keep, i, 16);
        float inx = __shfl_sync(FULL, v_nx, i, 16);
        float iny = __shfl_sync(FULL, v_ny, i, 16);
        float inz = __shfl_sync(FULL, v_nz, i, 16);
        float dt = inx * v_nx + iny * v_ny + inz * v_nz;
        if (ki && pos > i && dt > COS_THR) keep = 0;
    }

    // stable partition destination: kept first (in order), dropped after (in order)
    unsigned ball = __ballot_sync(FULL, keep);
    unsigned seg = (ball >> (l & 16)) & 0xFFFFu;
    int kept_before = __popc(seg & ((1u << pos) - 1));
    int total_kept  = __popc(seg);
    int dest = keep ? kept_before : total_kept + (pos - kept_before);

    float* o = out + (b * NH + dest) * 8;
    float4 r0 = keep ? make_float4(v_nx, v_ny, v_nz, v_px) : make_float4(0, 0, 0, 0);
    float4 r1 = keep ? make_float4(v_py, v_pz, v_cf, v_sd) : make_float4(0, 0, 0, 0);
    ((float4*)o)[0] = r0;
    ((float4*)o)[1] = r1;
}

extern "C" void kernel_launch(void* const* d_in, const int* in_sizes, int n_in,
                              void* d_out, int out_size) {
    const float* pts = nullptr;    // 12288 elems
    const float* ypred = nullptr;  // 256 elems
    const int* thr = nullptr;      // 1 elem
    for (int i = 0; i < n_in; i++) {
        if (in_sizes[i] == NB * NPTS * 3)    pts   = (const float*)d_in[i];
        else if (in_sizes[i] == NB * NH * 4) ypred = (const float*)d_in[i];
        else if (in_sizes[i] == 1)           thr   = (const int*)d_in[i];
    }
    float* out = (float*)d_out;

    plane_validator_kernel<<<NBLOCKS, THREADS>>>(pts, ypred, thr, out);
}

// round 5
// speedup vs baseline: 1.3014x; 1.3014x over previous
#include <cuda_runtime.h>

// PlaneValidator: symmetric-chamfer between 1024 points and their per-plane
// reflections, then per-batch conf ranking + angular NMS.  Single fused kernel:
// last-arriving block performs the (warp-parallel) finalization.
//
//  - D[n,m] = |p_n - r_m|^2 is SYMMETRIC (reflection = involutive isometry),
//    so sde = 2 * mean_n min_m D.
//  - min_m (P2[n] + R2[m] - 2 p_n.r_m) = P2[n] + min_m (R2[m] - 2 p_n.r_m):
//    inner loop is 1 LDS.128 + 6 FFMA + 2 FMNMX per 2 pairs, unroll 16,
//    dual min-accumulators per row to shorten the serial FMNMX chain.

#define NB 4
#define NPTS 1024
#define NH 16
#define THREADS 256
#define ROW_CHUNK 512           // 2 chunks per (b,h); 2 rows per thread
#define NBLOCKS (NB * NH * 2)   // 128

#define COS_THR 0.8660254037844387f
#define FULL 0xFFFFFFFFu

__device__ float g_part[NBLOCKS];   // per-block partial sums (rewritten every launch)
__device__ int   g_count = 0;       // arrival counter (self-resetting)

__global__ __launch_bounds__(THREADS, 1) void plane_validator_kernel(
        const float* __restrict__ pts, const float* __restrict__ ypred,
        const int* __restrict__ thr_ptr, float* __restrict__ out) {
    const int bid = blockIdx.x;
    const int bh  = bid >> 1;          // (b,h) pair
    const int rc  = bid & 1;           // row chunk
    const int t   = threadIdx.x;

    // ---------------- chamfer phase ----------------
    const float* yp = ypred + bh * 4;
    const float nx = yp[0], ny = yp[1], nz = yp[2], dpl = yp[3];
    const float inv = 1.0f / sqrtf(nx * nx + ny * ny + nz * nz);
    const float nhx = nx * inv, nhy = ny * inv, nhz = nz * inv;
    const float dh  = dpl * inv;

    const float* pb = pts + (bh >> 4) * (NPTS * 3);

    // Stage columns: reflections as float4(-2rx, -2ry, -2rz, |r|^2)
    __shared__ float4 sB[NPTS];
    for (int i = t; i < NPTS; i += THREADS) {
        float px = pb[i * 3 + 0], py = pb[i * 3 + 1], pz = pb[i * 3 + 2];
        float proj = fmaf(px, nhx, fmaf(py, nhy, fmaf(pz, nhz, dh)));
        float s = -2.0f * proj;
        float rx = fmaf(s, nhx, px);
        float ry = fmaf(s, nhy, py);
        float rz = fmaf(s, nhz, pz);
        float r2 = fmaf(rx, rx, fmaf(ry, ry, rz * rz));
        sB[i] = make_float4(-2.0f * rx, -2.0f * ry, -2.0f * rz, r2);
    }

    // This thread's 2 rows (plain points) + squared norms
    float ax[2], ay[2], az[2], p2[2];
#pragma unroll
    for (int k = 0; k < 2; k++) {
        int r = rc * ROW_CHUNK + k * THREADS + t;
        float px = pb[r * 3 + 0], py = pb[r * 3 + 1], pz = pb[r * 3 + 2];
        ax[k] = px; ay[k] = py; az[k] = pz;
        p2[k] = fmaf(px, px, fmaf(py, py, pz * pz));
    }
    __syncthreads();

    // e_m = R2[m] - 2 p.r_m ; row-min of D = p2 + min e.
    // Dual accumulators per row (even/odd m) break the serial FMNMX chain.
    float b0a = 3.4e38f, b0b = 3.4e38f, b1a = 3.4e38f, b1b = 3.4e38f;
#pragma unroll 16
    for (int m = 0; m < NPTS; m += 2) {
        float4 q0 = sB[m];
        float4 q1 = sB[m + 1];
        float e0a = fmaf(ax[0], q0.x, fmaf(ay[0], q0.y, fmaf(az[0], q0.z, q0.w)));
        float e1a = fmaf(ax[1], q0.x, fmaf(ay[1], q0.y, fmaf(az[1], q0.z, q0.w)));
        float e0b = fmaf(ax[0], q1.x, fmaf(ay[0], q1.y, fmaf(az[0], q1.z, q1.w)));
        float e1b = fmaf(ax[1], q1.x, fmaf(ay[1], q1.y, fmaf(az[1], q1.z, q1.w)));
        b0a = fminf(b0a, e0a);
        b1a = fminf(b1a, e1a);
        b0b = fminf(b0b, e0b);
        b1b = fminf(b1b, e1b);
    }
    float acc = (fminf(b0a, b0b) + p2[0]) + (fminf(b1a, b1b) + p2[1]);

#pragma unroll
    for (int o = 16; o > 0; o >>= 1)
        acc += __shfl_down_sync(FULL, acc, o);

    __shared__ float wsum[THREADS / 32];
    __shared__ int s_last;
    if ((t & 31) == 0) wsum[t >> 5] = acc;
    __syncthreads();
    if (t == 0) {
        float s = 0.0f;
#pragma unroll
        for (int i = 0; i < THREADS / 32; i++) s += wsum[i];
        g_part[bid] = s;                         // raw sum of 512 row-mins
        __threadfence();                         // publish before arrival
        int old = atomicAdd(&g_count, 1);
        s_last = (old == NBLOCKS - 1);
        if (old == NBLOCKS - 1) g_count = 0;     // reset for next graph replay
    }
    __syncthreads();
    if (!s_last) return;

    // ---------------- finalize phase (last block only; lanes 0..63) ----------------
    __shared__ float s_ex[8][64];   // exchange: nx,ny,nz,px,py,pz,cf,sd by sorted pos

    const int l = t;
    float v_nx = 0, v_ny = 0, v_nz = 0, v_px = 0, v_py = 0, v_pz = 0, v_cf = 0, v_sd = 0;
    int pos = l & 15, b = l >> 4;

    if (l < 64) {
        // threshold: decode int32 vs float32 bit pattern defensively
        int tv = thr_ptr[0];
        float tf = __int_as_float(tv);
        float thr = (tf >= 1e-6f && tf <= 1e9f) ? tf : (float)tv;

        const float* yq = ypred + l * 4;
        float qx = yq[0], qy = yq[1], qz = yq[2], qd = yq[3];
        float qi = 1.0f / sqrtf(qx * qx + qy * qy + qz * qz);
        v_nx = qx * qi; v_ny = qy * qi; v_nz = qz * qi;
        float qdh = qd * qi;
        v_px = -qdh * v_nx; v_py = -qdh * v_ny; v_pz = -qdh * v_nz;

        // sde = 2 * mean(row mins): combine the two chunk partials
        volatile float* gp = g_part;
        v_sd = (gp[2 * l] + gp[2 * l + 1]) * (2.0f / (float)NPTS);

        // group min/max over 16 lanes
        float mn = v_sd, mx = v_sd;
#pragma unroll
        for (int o = 8; o > 0; o >>= 1) {
            mn = fminf(mn, __shfl_xor_sync(FULL, mn, o, 16));
            mx = fmaxf(mx, __shfl_xor_sync(FULL, mx, o, 16));
        }
        v_cf = 1.0f - (v_sd - mn) / (mx - mn);

        // stable descending rank (== stable argsort(-cf))
        int rank = 0;
#pragma unroll
        for (int j = 0; j < NH; j++) {
            float cfj = __shfl_sync(FULL, v_cf, j, 16);
            rank += (cfj > v_cf) || (cfj == v_cf && j < pos);
        }
        int slot = b * NH + rank;
        s_ex[0][slot] = v_nx; s_ex[1][slot] = v_ny; s_ex[2][slot] = v_nz;
        s_ex[3][slot] = v_px; s_ex[4][slot] = v_py; s_ex[5][slot] = v_pz;
        s_ex[6][slot] = v_cf; s_ex[7][slot] = v_sd;
        v_cf = thr;  // carry thr across the barrier
    }
    __syncthreads();
    if (l >= 64) return;

    float thr = v_cf;
    v_nx = s_ex[0][l]; v_ny = s_ex[1][l]; v_nz = s_ex[2][l];
    v_px = s_ex[3][l]; v_py = s_ex[4][l]; v_pz = s_ex[5][l];
    v_cf = s_ex[6][l]; v_sd = s_ex[7][l];

    // sequential NMS over sorted positions, live keep bits
    int keep = (v_sd <= thr);
#pragma unroll
    for (int i = 0; i < NH; i++) {
        int   ki  = __shfl_sync(FULL, keep, i, 16);
        float inx = __shfl_sync(FULL, v_nx, i, 16);
        float iny = __shfl_sync(FULL, v_ny, i, 16);
        float inz = __shfl_sync(FULL, v_nz, i, 16);
        float dt = inx * v_nx + iny * v_ny + inz * v_nz;
        if (ki && pos > i && dt > COS_THR) keep = 0;
    }

    // stable partition destination: kept first (in order), dropped after (in order)
    unsigned ball = __ballot_sync(FULL, keep);
    unsigned seg = (ball >> (l & 16)) & 0xFFFFu;
    int kept_before = __popc(seg & ((1u << pos) - 1));
    int total_kept  = __popc(seg);
    int dest = keep ? kept_before : total_kept + (pos - kept_before);

    float* o = out + (b * NH + dest) * 8;
    float4 r0 = keep ? make_float4(v_nx, v_ny, v_nz, v_px) : make_float4(0, 0, 0, 0);
    float4 r1 = keep ? make_float4(v_py, v_pz, v_cf, v_sd) : make_float4(0, 0, 0, 0);
    ((float4*)o)[0] = r0;
    ((float4*)o)[1] = r1;
}

extern "C" void kernel_launch(void* const* d_in, const int* in_sizes, int n_in,
                              void* d_out, int out_size) {
    const float* pts = nullptr;    // 12288 elems
    const float* ypred = nullptr;  // 256 elems
    const int* thr = nullptr;      // 1 elem
    for (int i = 0; i < n_in; i++) {
        if (in_sizes[i] == NB * NPTS * 3)    pts   = (const float*)d_in[i];
        else if (in_sizes[i] == NB * NH * 4) ypred = (const float*)d_in[i];
        else if (in_sizes[i] == 1)           thr   = (const int*)d_in[i];
    }
    float* out = (float*)d_out;

    plane_validator_kernel<<<NBLOCKS, THREADS>>>(pts, ypred, thr, out);
}